// round 9
// baseline (speedup 1.0000x reference)
#include <cuda_runtime.h>
#include <cuda_bf16.h>
#include <cstdint>

// Problem constants
#define GM 4608   // 512 * 9 rows on both sides
#define GK 3840   // feature dim (bytes per row in int8)

// ---------------- device scratch (static globals: no runtime allocs) ----------------
__device__ __align__(256) int8_t g_A8[(size_t)GM * GK];   // query, int8 (per-row scaled)
__device__ __align__(256) int8_t g_B8[(size_t)GM * GK];   // target, int8
__device__ float g_sa[GM];
__device__ float g_sb[GM];
__device__ __align__(256) float g_S[(size_t)GM * GM];     // similarity matrix (85 MB)
__device__ float g_f2f[512 * 512];
__device__ float g_x1[32 * 256 * 256];
__device__ float g_x2[64 * 128 * 128];
__device__ float g_x3[128 * 128 * 128];
__device__ float g_rowmax[128];

// ---------------- per-row int8 quantization (symmetric, scale = rowmax/127) -------
__global__ __launch_bounds__(256) void quantize_kernel(const float* __restrict__ q,
                                                       const float* __restrict__ tg) {
    const int row = blockIdx.x;
    const int isB = blockIdx.y;
    const float* src = (isB ? tg : q) + (size_t)row * GK;
    int8_t* dst = (isB ? g_B8 : g_A8) + (size_t)row * GK;
    const int t = threadIdx.x;

    float v[15];
    float m = 0.f;
#pragma unroll
    for (int j = 0; j < 15; j++) {
        v[j] = src[j * 256 + t];
        m = fmaxf(m, fabsf(v[j]));
    }
#pragma unroll
    for (int o = 16; o > 0; o >>= 1) m = fmaxf(m, __shfl_xor_sync(0xffffffffu, m, o));
    __shared__ float wm[8];
    __shared__ float smax;
    if ((t & 31) == 0) wm[t >> 5] = m;
    __syncthreads();
    if (t == 0) {
        float z = wm[0];
#pragma unroll
        for (int i = 1; i < 8; i++) z = fmaxf(z, wm[i]);
        smax = fmaxf(z, 1e-20f);
        (isB ? g_sb : g_sa)[row] = smax * (1.f / 127.f);
    }
    __syncthreads();
    const float inv = 127.f / smax;
#pragma unroll
    for (int j = 0; j < 15; j++)
        dst[j * 256 + t] = (int8_t)__float2int_rn(v[j] * inv);
}

// =================================================================================
// GEMM: S = (A8 @ B8^T) * sa*sb  (int8 in, s32 accum, fp32 out), mma.sync IMMA
// CTA tile 128(M) x 128(N) x 128(K int8), 3-stage smem ring, 4 warps (2x2),
// warp tile 64x64, 2 CTAs/SM (96 KB smem each), ONE __syncthreads per k-iter.
// Fragment bytes for m16n8k32.s8 == m16n8k16.bf16 -> same ldmatrix/swizzle code.
// =================================================================================
#define BM 128
#define BN 128
#define BKB 128          // K bytes (int8 elems) per stage
#define STAGES 3
#define NITER (GK / BKB)   // 30

#define SA_STAGE (BM * BKB)           // 16384 B
#define SB_STAGE (BN * BKB)           // 16384 B
#define SB_BASE  (STAGES * SA_STAGE)  // 49152
#define SMEM_TOTAL (SB_BASE + STAGES * SB_STAGE)   // 98304 (96 KB)

__device__ __forceinline__ uint32_t smem_u32(const void* p) {
    return (uint32_t)__cvta_generic_to_shared(p);
}
__device__ __forceinline__ void cp_async16(uint32_t s, const void* g) {
    asm volatile("cp.async.cg.shared.global [%0],[%1],16;\n" ::"r"(s), "l"(g));
}
// SW128-style xor swizzle: permutes 16B units within each 1KB (8-row) block
__device__ __forceinline__ uint32_t sw128(uint32_t off) {
    return off ^ ((off >> 3) & 0x70);
}

__global__ __launch_bounds__(128, 2) void gemm_kernel() {
    extern __shared__ char smem[];
    const uint32_t sbase = smem_u32(smem);

    const int tid  = threadIdx.x;
    const int lane = tid & 31;
    const int wid  = tid >> 5;          // 0..3
    const int m0 = blockIdx.y * BM;
    const int n0 = blockIdx.x * BN;
    const int wm = (wid & 1) * 64;      // 2 warps over M
    const int wn = (wid >> 1) * 64;     // 2 warps over N

    int acc[4][8][4];
#pragma unroll
    for (int i = 0; i < 4; i++)
#pragma unroll
        for (int j = 0; j < 8; j++)
#pragma unroll
            for (int k = 0; k < 4; k++) acc[i][j][k] = 0;

    // ---- stage loader: A 1024 + B 1024 16B-chunks over 128 threads ----
    auto load_stage = [&](int slot, int k0) {
        const uint32_t abase = sbase + slot * SA_STAGE;
        const uint32_t bbase = sbase + SB_BASE + slot * SB_STAGE;
#pragma unroll
        for (int i = 0; i < 8; i++) {
            const int c = tid + 128 * i;
            const int row = c >> 3, col = c & 7;
            cp_async16(abase + sw128(row * 128 + col * 16),
                       g_A8 + (size_t)(m0 + row) * GK + k0 + col * 16);
        }
#pragma unroll
        for (int i = 0; i < 8; i++) {
            const int c = tid + 128 * i;
            const int row = c >> 3, col = c & 7;
            cp_async16(bbase + sw128(row * 128 + col * 16),
                       g_B8 + (size_t)(n0 + row) * GK + k0 + col * 16);
        }
        asm volatile("cp.async.commit_group;\n" ::);
    };

    // ---- prologue: fill STAGES-1 = 2 stages ----
#pragma unroll
    for (int s = 0; s < STAGES - 1; s++) load_stage(s, s * BKB);

    int slot = 0;
    for (int kt = 0; kt < NITER; kt++) {
        asm volatile("cp.async.wait_group %0;\n" ::"n"(STAGES - 2));
        __syncthreads();
        if (kt + STAGES - 1 < NITER) {
            load_stage((kt + STAGES - 1) % STAGES, (kt + STAGES - 1) * BKB);
        } else {
            asm volatile("cp.async.commit_group;\n" ::);
        }

        const uint32_t abase = sbase + slot * SA_STAGE;
        const uint32_t bbase = sbase + SB_BASE + slot * SB_STAGE;

#pragma unroll
        for (int ks = 0; ks < 4; ks++) {     // 4 x k32 int8 steps
            uint32_t a[4][4];
#pragma unroll
            for (int mt = 0; mt < 4; mt++) {
                const int r = wm + mt * 16 + (lane & 15);
                const uint32_t addr = abase + sw128(r * 128 + ks * 32 + (lane >> 4) * 16);
                asm volatile("ldmatrix.sync.aligned.m8n8.x4.shared.b16 {%0,%1,%2,%3},[%4];\n"
                             : "=r"(a[mt][0]), "=r"(a[mt][1]), "=r"(a[mt][2]), "=r"(a[mt][3])
                             : "r"(addr));
            }
            uint32_t b[8][2];
#pragma unroll
            for (int np = 0; np < 4; np++) {
                const int r = wn + np * 16 + (lane >> 4) * 8 + (lane & 7);
                const uint32_t addr = bbase + sw128(r * 128 + ks * 32 + ((lane >> 3) & 1) * 16);
                asm volatile("ldmatrix.sync.aligned.m8n8.x4.shared.b16 {%0,%1,%2,%3},[%4];\n"
                             : "=r"(b[2 * np][0]), "=r"(b[2 * np][1]),
                               "=r"(b[2 * np + 1][0]), "=r"(b[2 * np + 1][1])
                             : "r"(addr));
            }
#pragma unroll
            for (int mt = 0; mt < 4; mt++)
#pragma unroll
                for (int nt = 0; nt < 8; nt++) {
                    asm volatile(
                        "mma.sync.aligned.m16n8k32.row.col.s32.s8.s8.s32 "
                        "{%0,%1,%2,%3},{%4,%5,%6,%7},{%8,%9},{%0,%1,%2,%3};\n"
                        : "+r"(acc[mt][nt][0]), "+r"(acc[mt][nt][1]),
                          "+r"(acc[mt][nt][2]), "+r"(acc[mt][nt][3])
                        : "r"(a[mt][0]), "r"(a[mt][1]), "r"(a[mt][2]), "r"(a[mt][3]),
                          "r"(b[nt][0]), "r"(b[nt][1]));
                }
        }
        if (++slot == STAGES) slot = 0;
    }

    // ---- epilogue: dequantize and write fp32 tile to g_S ----
#pragma unroll
    for (int mt = 0; mt < 4; mt++) {
        const int r = m0 + wm + mt * 16 + (lane >> 2);
        const float sa0 = g_sa[r];
        const float sa8 = g_sa[r + 8];
#pragma unroll
        for (int nt = 0; nt < 8; nt++) {
            const int c = n0 + wn + nt * 8 + (lane & 3) * 2;
            const float sb0 = g_sb[c];
            const float sb1 = g_sb[c + 1];
            float* p0 = g_S + (size_t)r * GM + c;
            p0[0] = (float)acc[mt][nt][0] * sa0 * sb0;
            p0[1] = (float)acc[mt][nt][1] * sa0 * sb1;
            float* p1 = p0 + (size_t)8 * GM;
            p1[0] = (float)acc[mt][nt][2] * sa8 * sb0;
            p1[1] = (float)acc[mt][nt][3] * sa8 * sb1;
        }
    }
}

// ---------------- f2f[i][j] = mean_o max_p S[i*9+o][j*9+p] ----------------
__global__ void f2f_kernel() {
    const int idx = blockIdx.x * blockDim.x + threadIdx.x;
    if (idx >= 512 * 512) return;
    const int i = idx >> 9, j = idx & 511;
    float s = 0.f;
#pragma unroll
    for (int o = 0; o < 9; o++) {
        const float* row = g_S + (size_t)(i * 9 + o) * GM + j * 9;
        float m = row[0];
#pragma unroll
        for (int p = 1; p < 9; p++) m = fmaxf(m, row[p]);
        s += m;
    }
    g_f2f[idx] = s * (1.f / 9.f);
}

// ---------------- direct 3x3 conv (+relu, optional 2x2 maxpool) ----------------
template <int LAYER>
__global__ __launch_bounds__(256) void conv_kernel(const float* __restrict__ w,
                                                   const float* __restrict__ bias) {
    constexpr int CIN  = (LAYER == 1) ? 1 : (LAYER == 2) ? 32 : 64;
    constexpr int H    = (LAYER == 1) ? 512 : (LAYER == 2) ? 256 : 128;
    constexpr bool POOL = (LAYER != 3);
    const float* in = (LAYER == 1) ? g_f2f : (LAYER == 2) ? g_x1 : g_x2;
    float* out = (LAYER == 1) ? g_x1 : (LAYER == 2) ? g_x2 : g_x3;

    __shared__ float tile[34][34];
    __shared__ float wsh[8][9];

    const int tid = threadIdx.x;
    const int tx = tid & 15, ty = tid >> 4;
    const int x0 = blockIdx.x * 32, y0 = blockIdx.y * 32;
    const int ocg = blockIdx.z;

    float acc[8][4] = {};

    for (int ic = 0; ic < CIN; ic++) {
        for (int idx = tid; idx < 34 * 34; idx += 256) {
            const int r = idx / 34, c = idx - r * 34;
            const int gy = y0 + r - 1, gx = x0 + c - 1;
            float v = 0.f;
            if (gy >= 0 && gy < H && gx >= 0 && gx < H)
                v = in[(size_t)ic * H * H + (size_t)gy * H + gx];
            (&tile[0][0])[idx] = v;
        }
        if (tid < 72)
            wsh[tid / 9][tid % 9] = w[(size_t)((ocg * 8 + tid / 9) * CIN + ic) * 9 + tid % 9];
        __syncthreads();

        float v[4][4];
#pragma unroll
        for (int dy = 0; dy < 4; dy++)
#pragma unroll
            for (int dx = 0; dx < 4; dx++) v[dy][dx] = tile[2 * ty + dy][2 * tx + dx];

#pragma unroll
        for (int oc = 0; oc < 8; oc++) {
            float wr[9];
#pragma unroll
            for (int t2 = 0; t2 < 9; t2++) wr[t2] = wsh[oc][t2];
#pragma unroll
            for (int py = 0; py < 2; py++)
#pragma unroll
                for (int px = 0; px < 2; px++) {
                    float s = acc[oc][py * 2 + px];
#pragma unroll
                    for (int kh = 0; kh < 3; kh++)
#pragma unroll
                        for (int kw = 0; kw < 3; kw++)
                            s += v[py + kh][px + kw] * wr[kh * 3 + kw];
                    acc[oc][py * 2 + px] = s;
                }
        }
        __syncthreads();
    }

#pragma unroll
    for (int oc = 0; oc < 8; oc++) {
        const float b = bias[ocg * 8 + oc];
        if (POOL) {
            constexpr int Hp = H / 2;
            float m = fmaxf(fmaxf(acc[oc][0], acc[oc][1]), fmaxf(acc[oc][2], acc[oc][3])) + b;
            m = fmaxf(m, 0.f);
            out[(size_t)(ocg * 8 + oc) * Hp * Hp + (size_t)(blockIdx.y * 16 + ty) * Hp +
                (blockIdx.x * 16 + tx)] = m;
        } else {
#pragma unroll
            for (int py = 0; py < 2; py++)
#pragma unroll
                for (int px = 0; px < 2; px++)
                    out[(size_t)(ocg * 8 + oc) * H * H + (size_t)(y0 + 2 * ty + py) * H +
                        (x0 + 2 * tx + px)] = fmaxf(acc[oc][py * 2 + px] + b, 0.f);
        }
    }
}

// ---------------- 1x1 conv + clip + per-row max ----------------
__global__ void final_rowmax_kernel(const float* __restrict__ wf, const float* __restrict__ bf) {
    const int h = blockIdx.x;    // 0..127
    const int w = threadIdx.x;   // 0..127
    float s = bf[0];
#pragma unroll 8
    for (int c = 0; c < 128; c++) s += wf[c] * g_x3[(size_t)c * 128 * 128 + h * 128 + w];
    s = fminf(fmaxf(s, -1.f), 1.f);
    __shared__ float red[128];
    red[w] = s;
    __syncthreads();
    for (int st = 64; st > 0; st >>= 1) {
        if (w < st) red[w] = fmaxf(red[w], red[w + st]);
        __syncthreads();
    }
    if (w == 0) g_rowmax[h] = red[0];
}

__global__ void final_mean_kernel(float* __restrict__ out) {
    const int t = threadIdx.x;   // 0..127
    __shared__ float red[128];
    red[t] = g_rowmax[t];
    __syncthreads();
    for (int st = 64; st > 0; st >>= 1) {
        if (t < st) red[t] += red[t + st];
        __syncthreads();
    }
    if (t == 0) out[0] = red[0] / 128.f;
}

// ---------------- launch ----------------
extern "C" void kernel_launch(void* const* d_in, const int* in_sizes, int n_in,
                              void* d_out, int out_size) {
    const float* q  = (const float*)d_in[0];
    const float* t  = (const float*)d_in[1];
    const float* w1 = (const float*)d_in[2];
    const float* b1 = (const float*)d_in[3];
    const float* w2 = (const float*)d_in[4];
    const float* b2 = (const float*)d_in[5];
    const float* w3 = (const float*)d_in[6];
    const float* b3 = (const float*)d_in[7];
    const float* wf = (const float*)d_in[8];
    const float* bf = (const float*)d_in[9];

    // idempotent, not a stream op (graph-capture safe)
    cudaFuncSetAttribute(gemm_kernel, cudaFuncAttributeMaxDynamicSharedMemorySize, SMEM_TOTAL);

    quantize_kernel<<<dim3(GM, 2), 256>>>(q, t);
    gemm_kernel<<<dim3(GM / BN, GM / BM), 128, SMEM_TOTAL>>>();
    f2f_kernel<<<1024, 256>>>();
    conv_kernel<1><<<dim3(16, 16, 4), 256>>>(w1, b1);
    conv_kernel<2><<<dim3(8, 8, 8), 256>>>(w2, b2);
    conv_kernel<3><<<dim3(4, 4, 16), 256>>>(w3, b3);
    final_rowmax_kernel<<<128, 128>>>(wf, bf);
    final_mean_kernel<<<1, 128>>>((float*)d_out);
}

// round 10
// speedup vs baseline: 2.1202x; 2.1202x over previous
#include <cuda_runtime.h>
#include <cuda_bf16.h>
#include <cstdint>

// Problem constants
#define GM 4608   // 512 * 9 rows on both sides
#define GK 3840   // feature dim

// ---------------- device scratch (static globals: no runtime allocs) ----------------
__device__ __align__(256) __nv_bfloat16 g_A[(size_t)GM * GK];   // query, bf16
__device__ __align__(256) __nv_bfloat16 g_B[(size_t)GM * GK];   // target, bf16
__device__ __align__(256) float g_S[(size_t)GM * GM];           // similarity matrix (85 MB)
__device__ float g_f2f[512 * 512];
__device__ float g_x1[32 * 256 * 256];
__device__ float g_x2[64 * 128 * 128];
__device__ float g_x3[128 * 128 * 128];
__device__ float g_rowmax[128];

// ---------------- fp32 -> bf16 conversion ----------------
__global__ void convert_kernel(const float4* __restrict__ q, const float4* __restrict__ t) {
    const size_t n = (size_t)GM * GK / 4;
    __nv_bfloat162* A2 = (__nv_bfloat162*)g_A;
    __nv_bfloat162* B2 = (__nv_bfloat162*)g_B;
    for (size_t i = (size_t)blockIdx.x * blockDim.x + threadIdx.x; i < n;
         i += (size_t)gridDim.x * blockDim.x) {
        float4 a = q[i];
        float4 b = t[i];
        A2[2 * i]     = __floats2bfloat162_rn(a.x, a.y);
        A2[2 * i + 1] = __floats2bfloat162_rn(a.z, a.w);
        B2[2 * i]     = __floats2bfloat162_rn(b.x, b.y);
        B2[2 * i + 1] = __floats2bfloat162_rn(b.z, b.w);
    }
}

// =================================================================================
// GEMM: S = A @ B^T (bf16 in, fp32 accum), mma.sync multistage pipeline
// CTA tile 128(M) x 128(N) x 64(K), 3-stage smem ring, 4 warps (2x2), warp 64x64,
// 2 CTAs/SM (96 KB smem each), ONE __syncthreads per k-iter.  (Round-5 proven.)
// =================================================================================
#define BM 128
#define BN 128
#define BK 64
#define STAGES 3
#define NITER (GK / BK)   // 60

#define SA_STAGE (BM * BK * 2)        // 16384 B
#define SB_STAGE (BN * BK * 2)        // 16384 B
#define SB_BASE  (STAGES * SA_STAGE)  // 49152
#define SMEM_TOTAL (SB_BASE + STAGES * SB_STAGE)   // 98304 (96 KB)

__device__ __forceinline__ uint32_t smem_u32(const void* p) {
    return (uint32_t)__cvta_generic_to_shared(p);
}
__device__ __forceinline__ void cp_async16(uint32_t s, const void* g) {
    asm volatile("cp.async.cg.shared.global [%0],[%1],16;\n" ::"r"(s), "l"(g));
}
// SW128-style xor swizzle: permutes 16B units within each 1KB (8-row) block
__device__ __forceinline__ uint32_t sw128(uint32_t off) {
    return off ^ ((off >> 3) & 0x70);
}

__global__ __launch_bounds__(128, 2) void gemm_kernel() {
    extern __shared__ char smem[];
    const uint32_t sbase = smem_u32(smem);

    const int tid  = threadIdx.x;
    const int lane = tid & 31;
    const int wid  = tid >> 5;          // 0..3
    const int m0 = blockIdx.y * BM;
    const int n0 = blockIdx.x * BN;
    const int wm = (wid & 1) * 64;      // 2 warps over M
    const int wn = (wid >> 1) * 64;     // 2 warps over N

    float acc[4][8][4];
#pragma unroll
    for (int i = 0; i < 4; i++)
#pragma unroll
        for (int j = 0; j < 8; j++)
#pragma unroll
            for (int k = 0; k < 4; k++) acc[i][j][k] = 0.f;

    // ---- stage loader: A 1024 + B 1024 16B-chunks over 128 threads ----
    auto load_stage = [&](int slot, int k0) {
        const uint32_t abase = sbase + slot * SA_STAGE;
        const uint32_t bbase = sbase + SB_BASE + slot * SB_STAGE;
#pragma unroll
        for (int i = 0; i < 8; i++) {
            const int c = tid + 128 * i;
            const int row = c >> 3, col = c & 7;
            cp_async16(abase + sw128(row * 128 + col * 16),
                       g_A + (size_t)(m0 + row) * GK + k0 + col * 8);
        }
#pragma unroll
        for (int i = 0; i < 8; i++) {
            const int c = tid + 128 * i;
            const int row = c >> 3, col = c & 7;
            cp_async16(bbase + sw128(row * 128 + col * 16),
                       g_B + (size_t)(n0 + row) * GK + k0 + col * 8);
        }
        asm volatile("cp.async.commit_group;\n" ::);
    };

    // ---- prologue: fill STAGES-1 = 2 stages ----
#pragma unroll
    for (int s = 0; s < STAGES - 1; s++) load_stage(s, s * BK);

    int slot = 0;
    for (int kt = 0; kt < NITER; kt++) {
        asm volatile("cp.async.wait_group %0;\n" ::"n"(STAGES - 2));
        __syncthreads();
        if (kt + STAGES - 1 < NITER) {
            load_stage((kt + STAGES - 1) % STAGES, (kt + STAGES - 1) * BK);
        } else {
            asm volatile("cp.async.commit_group;\n" ::);
        }

        const uint32_t abase = sbase + slot * SA_STAGE;
        const uint32_t bbase = sbase + SB_BASE + slot * SB_STAGE;

#pragma unroll
        for (int ks = 0; ks < 4; ks++) {
            uint32_t a[4][4];
#pragma unroll
            for (int mt = 0; mt < 4; mt++) {
                const int r  = wm + mt * 16 + (lane & 15);
                const int kk = ks * 16 + (lane >> 4) * 8;
                const uint32_t addr = abase + sw128(r * 128 + kk * 2);
                asm volatile("ldmatrix.sync.aligned.m8n8.x4.shared.b16 {%0,%1,%2,%3},[%4];\n"
                             : "=r"(a[mt][0]), "=r"(a[mt][1]), "=r"(a[mt][2]), "=r"(a[mt][3])
                             : "r"(addr));
            }
            uint32_t b[8][2];
#pragma unroll
            for (int np = 0; np < 4; np++) {
                const int r  = wn + np * 16 + (lane >> 4) * 8 + (lane & 7);
                const int kk = ks * 16 + ((lane >> 3) & 1) * 8;
                const uint32_t addr = bbase + sw128(r * 128 + kk * 2);
                asm volatile("ldmatrix.sync.aligned.m8n8.x4.shared.b16 {%0,%1,%2,%3},[%4];\n"
                             : "=r"(b[2 * np][0]), "=r"(b[2 * np][1]),
                               "=r"(b[2 * np + 1][0]), "=r"(b[2 * np + 1][1])
                             : "r"(addr));
            }
#pragma unroll
            for (int mt = 0; mt < 4; mt++)
#pragma unroll
                for (int nt = 0; nt < 8; nt++) {
                    asm volatile(
                        "mma.sync.aligned.m16n8k16.row.col.f32.bf16.bf16.f32 "
                        "{%0,%1,%2,%3},{%4,%5,%6,%7},{%8,%9},{%0,%1,%2,%3};\n"
                        : "+f"(acc[mt][nt][0]), "+f"(acc[mt][nt][1]),
                          "+f"(acc[mt][nt][2]), "+f"(acc[mt][nt][3])
                        : "r"(a[mt][0]), "r"(a[mt][1]), "r"(a[mt][2]), "r"(a[mt][3]),
                          "r"(b[nt][0]), "r"(b[nt][1]));
                }
        }
        if (++slot == STAGES) slot = 0;
    }

    // ---- epilogue: write fp32 tile to g_S ----
#pragma unroll
    for (int mt = 0; mt < 4; mt++) {
        const int r = m0 + wm + mt * 16 + (lane >> 2);
#pragma unroll
        for (int nt = 0; nt < 8; nt++) {
            const int c = n0 + wn + nt * 8 + (lane & 3) * 2;
            float* p0 = g_S + (size_t)r * GM + c;
            p0[0] = acc[mt][nt][0];
            p0[1] = acc[mt][nt][1];
            float* p1 = p0 + (size_t)8 * GM;
            p1[0] = acc[mt][nt][2];
            p1[1] = acc[mt][nt][3];
        }
    }
}

// ---------------- f2f[i][j] = mean_o max_p S[i*9+o][j*9+p] ----------------
__global__ void f2f_kernel() {
    const int idx = blockIdx.x * blockDim.x + threadIdx.x;
    if (idx >= 512 * 512) return;
    const int i = idx >> 9, j = idx & 511;
    float s = 0.f;
#pragma unroll
    for (int o = 0; o < 9; o++) {
        const float* row = g_S + (size_t)(i * 9 + o) * GM + j * 9;
        float m = row[0];
#pragma unroll
        for (int p = 1; p < 9; p++) m = fmaxf(m, row[p]);
        s += m;
    }
    g_f2f[idx] = s * (1.f / 9.f);
}

// ---------------- conv layer 1 (CIN=1): simple tiled version ----------------
__global__ __launch_bounds__(256) void conv1_kernel(const float* __restrict__ w,
                                                    const float* __restrict__ bias) {
    constexpr int H = 512;
    const float* in = g_f2f;
    float* out = g_x1;

    __shared__ float tile[34][34];
    __shared__ float wsh[8][9];

    const int tid = threadIdx.x;
    const int tx = tid & 15, ty = tid >> 4;
    const int x0 = blockIdx.x * 32, y0 = blockIdx.y * 32;
    const int ocg = blockIdx.z;

    for (int idx = tid; idx < 34 * 34; idx += 256) {
        const int r = idx / 34, c = idx - r * 34;
        const int gy = y0 + r - 1, gx = x0 + c - 1;
        float v = 0.f;
        if (gy >= 0 && gy < H && gx >= 0 && gx < H) v = in[(size_t)gy * H + gx];
        (&tile[0][0])[idx] = v;
    }
    if (tid < 72) wsh[tid / 9][tid % 9] = w[(size_t)(ocg * 8 + tid / 9) * 9 + tid % 9];
    __syncthreads();

    float v[4][4];
#pragma unroll
    for (int dy = 0; dy < 4; dy++)
#pragma unroll
        for (int dx = 0; dx < 4; dx++) v[dy][dx] = tile[2 * ty + dy][2 * tx + dx];

#pragma unroll
    for (int oc = 0; oc < 8; oc++) {
        float wr[9];
#pragma unroll
        for (int t2 = 0; t2 < 9; t2++) wr[t2] = wsh[oc][t2];
        float p[4];
#pragma unroll
        for (int py = 0; py < 2; py++)
#pragma unroll
            for (int px = 0; px < 2; px++) {
                float s = 0.f;
#pragma unroll
                for (int kh = 0; kh < 3; kh++)
#pragma unroll
                    for (int kw = 0; kw < 3; kw++)
                        s += v[py + kh][px + kw] * wr[kh * 3 + kw];
                p[py * 2 + px] = s;
            }
        const float b = bias[ocg * 8 + oc];
        float m = fmaxf(fmaxf(p[0], p[1]), fmaxf(p[2], p[3])) + b;
        m = fmaxf(m, 0.f);
        out[(size_t)(ocg * 8 + oc) * 256 * 256 + (size_t)(blockIdx.y * 16 + ty) * 256 +
            (blockIdx.x * 16 + tx)] = m;
    }
}

// ---------------- conv layers 2/3: preloaded weights + double-buffered tile ------
// LAYER 2: 32->64, H=256, pool.  LAYER 3: 64->128, H=128, no pool.
template <int LAYER>
__global__ __launch_bounds__(256) void convN_kernel(const float* __restrict__ w,
                                                    const float* __restrict__ bias) {
    constexpr int CIN  = (LAYER == 2) ? 32 : 64;
    constexpr int H    = (LAYER == 2) ? 256 : 128;
    constexpr bool POOL = (LAYER == 2);
    const float* in = (LAYER == 2) ? g_x1 : g_x2;
    float* out = (LAYER == 2) ? g_x2 : g_x3;

    __shared__ float tile[2][34][34];
    __shared__ float wsh[CIN][8][9];

    const int tid = threadIdx.x;
    const int tx = tid & 15, ty = tid >> 4;
    const int x0 = blockIdx.x * 32, y0 = blockIdx.y * 32;
    const int ocg = blockIdx.z;

    // preload ALL weights for this ocg once
    for (int idx = tid; idx < CIN * 72; idx += 256) {
        const int ic = idx / 72, rem = idx - ic * 72;
        const int oc = rem / 9, k = rem - oc * 9;
        wsh[ic][oc][k] = w[(size_t)((ocg * 8 + oc) * CIN + ic) * 9 + k];
    }

    auto load_tile = [&](int ic, int buf) {
        const float* src = in + (size_t)ic * H * H;
        for (int idx = tid; idx < 34 * 34; idx += 256) {
            const int r = idx / 34, c = idx - r * 34;
            const int gy = y0 + r - 1, gx = x0 + c - 1;
            float v = 0.f;
            if (gy >= 0 && gy < H && gx >= 0 && gx < H) v = src[(size_t)gy * H + gx];
            (&tile[buf][0][0])[idx] = v;
        }
    };

    float acc[8][4] = {};

    load_tile(0, 0);
    __syncthreads();

    for (int ic = 0; ic < CIN; ic++) {
        // prefetch next channel's tile into the other buffer (overlaps compute)
        if (ic + 1 < CIN) load_tile(ic + 1, (ic + 1) & 1);

        const int buf = ic & 1;
        float v[4][4];
#pragma unroll
        for (int dy = 0; dy < 4; dy++)
#pragma unroll
            for (int dx = 0; dx < 4; dx++) v[dy][dx] = tile[buf][2 * ty + dy][2 * tx + dx];

#pragma unroll
        for (int oc = 0; oc < 8; oc++) {
            float wr[9];
#pragma unroll
            for (int t2 = 0; t2 < 9; t2++) wr[t2] = wsh[ic][oc][t2];
#pragma unroll
            for (int py = 0; py < 2; py++)
#pragma unroll
                for (int px = 0; px < 2; px++) {
                    float s = acc[oc][py * 2 + px];
#pragma unroll
                    for (int kh = 0; kh < 3; kh++)
#pragma unroll
                        for (int kw = 0; kw < 3; kw++)
                            s += v[py + kh][px + kw] * wr[kh * 3 + kw];
                    acc[oc][py * 2 + px] = s;
                }
        }
        __syncthreads();   // next-buf writes complete; cur buf free for iter ic+2
    }

#pragma unroll
    for (int oc = 0; oc < 8; oc++) {
        const float b = bias[ocg * 8 + oc];
        if (POOL) {
            constexpr int Hp = H / 2;
            float m = fmaxf(fmaxf(acc[oc][0], acc[oc][1]), fmaxf(acc[oc][2], acc[oc][3])) + b;
            m = fmaxf(m, 0.f);
            out[(size_t)(ocg * 8 + oc) * Hp * Hp + (size_t)(blockIdx.y * 16 + ty) * Hp +
                (blockIdx.x * 16 + tx)] = m;
        } else {
#pragma unroll
            for (int py = 0; py < 2; py++)
#pragma unroll
                for (int px = 0; px < 2; px++)
                    out[(size_t)(ocg * 8 + oc) * H * H + (size_t)(y0 + 2 * ty + py) * H +
                        (x0 + 2 * tx + px)] = fmaxf(acc[oc][py * 2 + px] + b, 0.f);
        }
    }
}

// ---------------- 1x1 conv + clip + per-row max ----------------
__global__ void final_rowmax_kernel(const float* __restrict__ wf, const float* __restrict__ bf) {
    const int h = blockIdx.x;    // 0..127
    const int w = threadIdx.x;   // 0..127
    float s = bf[0];
#pragma unroll 8
    for (int c = 0; c < 128; c++) s += wf[c] * g_x3[(size_t)c * 128 * 128 + h * 128 + w];
    s = fminf(fmaxf(s, -1.f), 1.f);
    __shared__ float red[128];
    red[w] = s;
    __syncthreads();
    for (int st = 64; st > 0; st >>= 1) {
        if (w < st) red[w] = fmaxf(red[w], red[w + st]);
        __syncthreads();
    }
    if (w == 0) g_rowmax[h] = red[0];
}

__global__ void final_mean_kernel(float* __restrict__ out) {
    const int t = threadIdx.x;   // 0..127
    __shared__ float red[128];
    red[t] = g_rowmax[t];
    __syncthreads();
    for (int st = 64; st > 0; st >>= 1) {
        if (t < st) red[t] += red[t + st];
        __syncthreads();
    }
    if (t == 0) out[0] = red[0] / 128.f;
}

// ---------------- launch ----------------
extern "C" void kernel_launch(void* const* d_in, const int* in_sizes, int n_in,
                              void* d_out, int out_size) {
    const float* q  = (const float*)d_in[0];
    const float* t  = (const float*)d_in[1];
    const float* w1 = (const float*)d_in[2];
    const float* b1 = (const float*)d_in[3];
    const float* w2 = (const float*)d_in[4];
    const float* b2 = (const float*)d_in[5];
    const float* w3 = (const float*)d_in[6];
    const float* b3 = (const float*)d_in[7];
    const float* wf = (const float*)d_in[8];
    const float* bf = (const float*)d_in[9];

    // idempotent, not a stream op (graph-capture safe)
    cudaFuncSetAttribute(gemm_kernel, cudaFuncAttributeMaxDynamicSharedMemorySize, SMEM_TOTAL);

    convert_kernel<<<4096, 256>>>((const float4*)q, (const float4*)t);
    gemm_kernel<<<dim3(GM / BN, GM / BM), 128, SMEM_TOTAL>>>();
    f2f_kernel<<<1024, 256>>>();
    conv1_kernel<<<dim3(16, 16, 4), 256>>>(w1, b1);
    convN_kernel<2><<<dim3(8, 8, 8), 256>>>(w2, b2);
    convN_kernel<3><<<dim3(4, 4, 16), 256>>>(w3, b3);
    final_rowmax_kernel<<<128, 128>>>(wf, bf);
    final_mean_kernel<<<1, 128>>>((float*)d_out);
}